// round 4
// baseline (speedup 1.0000x reference)
#include <cuda_runtime.h>
#include <cstdint>
#include <cstddef>

static constexpr int NN = 50000;   // nodes
static constexpr int NE = 800000;  // edges
// features: 128 -> 256 -> 128

// ---------------- scratch (device globals; no allocation allowed) -----------
__device__ int   g_is64;                     // edge_index dtype flag
__device__ int   g_cnt[NN];                  // in-degree (no self-loop)
__device__ int   g_cur[NN];                  // fill cursors
__device__ int   g_row[NN];                  // CSR row starts
__device__ int   g_csr[NE];                  // CSR src indices
__device__ float g_isd[NN];                  // 1/sqrt(deg), deg incl self-loop
__device__ float g_t1[(size_t)NN * 256];     // x @ W1
__device__ float g_z1[(size_t)NN * 256];     // relu(agg1 + b1)
__device__ float g_t2[(size_t)NN * 128];     // z1 @ W2
__device__ float g_z2[(size_t)NN * 128];     // relu(agg2 + b2)

// ---------------- edge_index dtype probe -------------------------------------
// Reads the first 1024 entries as int64 (8 KB — safely within even an int32
// buffer of 2*NE elements = 6.4 MB). If ALL are in [0, NN), data is int64;
// otherwise it is int32 (random int32 pairs seen as int64 are >> NN).
__global__ void k_detect(const void* __restrict__ ei) {
    __shared__ int bad;
    if (threadIdx.x == 0) bad = 0;
    __syncthreads();
    const long long* p = (const long long*)ei;
    for (int i = threadIdx.x; i < 1024; i += blockDim.x) {
        long long v = p[i];
        if (v < 0 || v >= NN) bad = 1;
    }
    __syncthreads();
    if (threadIdx.x == 0) g_is64 = bad ? 0 : 1;
}

__device__ __forceinline__ int edge_at(const void* __restrict__ ei, int idx) {
    if (g_is64) return (int)((const long long*)ei)[idx];
    return ((const int*)ei)[idx];
}

// ---------------- degree / CSR build ----------------------------------------
__global__ void k_init() {
    int i = blockIdx.x * blockDim.x + threadIdx.x;
    if (i < NN) { g_cnt[i] = 0; g_cur[i] = 0; }
}

__global__ void k_count(const void* __restrict__ ei) {
    int e = blockIdx.x * blockDim.x + threadIdx.x;
    if (e < NE) atomicAdd(&g_cnt[edge_at(ei, NE + e)], 1);
}

__global__ void k_isd() {
    int i = blockIdx.x * blockDim.x + threadIdx.x;
    if (i < NN) g_isd[i] = rsqrtf(1.0f + (float)g_cnt[i]);
}

// single-block exclusive scan of g_cnt -> g_row  (1024 threads x 49 elements)
__global__ void __launch_bounds__(1024) k_scan() {
    __shared__ int sh[2][1024];
    const int t  = threadIdx.x;
    const int CH = (NN + 1023) / 1024;   // 49
    const int b0 = t * CH;

    int local = 0;
    for (int i = 0; i < CH; i++) {
        int idx = b0 + i;
        if (idx < NN) local += g_cnt[idx];
    }
    int cur = 0;
    sh[cur][t] = local;
    __syncthreads();
    for (int off = 1; off < 1024; off <<= 1) {
        int nxt = cur ^ 1;
        int v = sh[cur][t];
        if (t >= off) v += sh[cur][t - off];
        sh[nxt][t] = v;
        __syncthreads();
        cur = nxt;
    }
    int run = (t == 0) ? 0 : sh[cur][t - 1];   // exclusive base for this chunk
    for (int i = 0; i < CH; i++) {
        int idx = b0 + i;
        if (idx < NN) { g_row[idx] = run; run += g_cnt[idx]; }
    }
}

__global__ void k_fill(const void* __restrict__ ei) {
    int e = blockIdx.x * blockDim.x + threadIdx.x;
    if (e >= NE) return;
    int s = edge_at(ei, e);
    int d = edge_at(ei, NE + e);
    int pos = g_row[d] + atomicAdd(&g_cur[d], 1);
    g_csr[pos] = s;
}

// ---------------- SIMT fp32 GEMM ---------------------------------------------
// C[M,N] = A[M,K] @ W[K,N] ; all dims compile-time via L1 flag.
// L1: A=x (arg), C=g_t1, K=128, N=256.  !L1: A=g_z1, C=g_t2, K=256, N=128.
template <bool L1>
__global__ void __launch_bounds__(256)
sgemm(const float* __restrict__ Aext, const float* __restrict__ W) {
    constexpr int K  = L1 ? 128 : 256;
    constexpr int N  = L1 ? 256 : 128;
    constexpr int BM = 64, BN = 64, BK = 16, TM = 4, TN = 4;

    const float* __restrict__ A = L1 ? Aext : g_z1;
    float* __restrict__       C = L1 ? g_t1 : g_t2;

    __shared__ float As[BM][BK];
    __shared__ float Bs[BK][BN];

    const int tid = threadIdx.x;
    const int tx  = tid % (BN / TN);   // 0..15
    const int ty  = tid / (BN / TN);   // 0..15
    const int bm0 = blockIdx.y * BM;
    const int bn0 = blockIdx.x * BN;

    float acc[TM][TN] = {};

    const int ar = tid / (BK / 4);         // 0..63
    const int ac = (tid % (BK / 4)) * 4;   // 0,4,8,12
    const int br = tid / (BN / 4);         // 0..15
    const int bc = (tid % (BN / 4)) * 4;   // 0..60

    #pragma unroll
    for (int k0 = 0; k0 < K; k0 += BK) {
        float4 av = make_float4(0.f, 0.f, 0.f, 0.f);
        int arow = bm0 + ar;
        if (arow < NN)
            av = *(const float4*)(A + (size_t)arow * K + k0 + ac);
        *(float4*)(&As[ar][ac]) = av;

        float4 wv = *(const float4*)(W + (size_t)(k0 + br) * N + bn0 + bc);
        *(float4*)(&Bs[br][bc]) = wv;
        __syncthreads();

        #pragma unroll
        for (int k = 0; k < BK; k++) {
            float a[TM], b[TN];
            #pragma unroll
            for (int i = 0; i < TM; i++) a[i] = As[ty * TM + i][k];
            #pragma unroll
            for (int j = 0; j < TN; j++) b[j] = Bs[k][tx * TN + j];
            #pragma unroll
            for (int i = 0; i < TM; i++)
                #pragma unroll
                for (int j = 0; j < TN; j++)
                    acc[i][j] += a[i] * b[j];
        }
        __syncthreads();
    }

    #pragma unroll
    for (int i = 0; i < TM; i++) {
        int r = bm0 + ty * TM + i;
        if (r >= NN) break;
        #pragma unroll
        for (int j = 0; j < TN; j += 4) {
            float4 v = make_float4(acc[i][j], acc[i][j + 1],
                                   acc[i][j + 2], acc[i][j + 3]);
            *(float4*)(C + (size_t)r * N + bn0 + tx * TN + j) = v;
        }
    }
}

// ---------------- aggregation: warp-per-node CSR gather ----------------------
// z[node] = relu( sum_{s in in(node)} h[s]*isd[s]*isd[node]
//                 + h[node]*isd[node]^2 + bias )
template <bool L1>
__global__ void __launch_bounds__(256)
k_agg(const float* __restrict__ bias) {
    constexpr int F  = L1 ? 256 : 128;
    constexpr int NV = F / 128;                    // float4 per lane
    const float* __restrict__ h = L1 ? g_t1 : g_t2;
    float* __restrict__       z = L1 ? g_z1 : g_z2;

    const int warp = threadIdx.x >> 5;
    const int lane = threadIdx.x & 31;
    const int node = blockIdx.x * 8 + warp;
    if (node >= NN) return;

    const float sd = g_isd[node];
    float4 acc[NV];
    {
        const float4* hd = (const float4*)(h + (size_t)node * F);
        const float w = sd * sd;   // self-loop norm
        #pragma unroll
        for (int v = 0; v < NV; v++) {
            float4 t = hd[lane + 32 * v];
            acc[v] = make_float4(t.x * w, t.y * w, t.z * w, t.w * w);
        }
    }

    const int beg = g_row[node];
    const int cnt = g_cnt[node];
    int e = 0;
    for (; e + 2 <= cnt; e += 2) {       // 2-way for MLP
        int s0 = g_csr[beg + e];
        int s1 = g_csr[beg + e + 1];
        float n0 = sd * g_isd[s0];
        float n1 = sd * g_isd[s1];
        const float4* h0 = (const float4*)(h + (size_t)s0 * F);
        const float4* h1 = (const float4*)(h + (size_t)s1 * F);
        #pragma unroll
        for (int v = 0; v < NV; v++) {
            float4 a = h0[lane + 32 * v];
            float4 b = h1[lane + 32 * v];
            acc[v].x += a.x * n0 + b.x * n1;
            acc[v].y += a.y * n0 + b.y * n1;
            acc[v].z += a.z * n0 + b.z * n1;
            acc[v].w += a.w * n0 + b.w * n1;
        }
    }
    if (e < cnt) {
        int s0 = g_csr[beg + e];
        float n0 = sd * g_isd[s0];
        const float4* h0 = (const float4*)(h + (size_t)s0 * F);
        #pragma unroll
        for (int v = 0; v < NV; v++) {
            float4 a = h0[lane + 32 * v];
            acc[v].x += a.x * n0;
            acc[v].y += a.y * n0;
            acc[v].z += a.z * n0;
            acc[v].w += a.w * n0;
        }
    }

    const float4* b4 = (const float4*)bias;
    float4* z4 = (float4*)(z + (size_t)node * F);
    #pragma unroll
    for (int v = 0; v < NV; v++) {
        float4 bb = b4[lane + 32 * v];
        float4 r;
        r.x = fmaxf(acc[v].x + bb.x, 0.f);
        r.y = fmaxf(acc[v].y + bb.y, 0.f);
        r.z = fmaxf(acc[v].z + bb.z, 0.f);
        r.w = fmaxf(acc[v].w + bb.w, 0.f);
        z4[lane + 32 * v] = r;
    }
}

// ---------------- final pool + fc --------------------------------------------
__global__ void k_out_init(const float* __restrict__ bfc, float* __restrict__ out) {
    out[0] = bfc[0];
}

// out += (1/NN) * sum_i dot(z2[i], Wfc)
__global__ void __launch_bounds__(256)
k_pool(const float* __restrict__ Wfc, float* __restrict__ out) {
    __shared__ float wf[128];
    int tid = threadIdx.x;
    if (tid < 128) wf[tid] = Wfc[tid];
    __syncthreads();

    int lane = tid & 31;
    int warp = tid >> 5;
    float acc = 0.f;

    for (int node = blockIdx.x * 8 + warp; node < NN; node += gridDim.x * 8) {
        const float4* row = (const float4*)(g_z2 + (size_t)node * 128);
        float4 v = row[lane];
        int f = lane * 4;
        acc += v.x * wf[f] + v.y * wf[f + 1] + v.z * wf[f + 2] + v.w * wf[f + 3];
    }
    #pragma unroll
    for (int o = 16; o; o >>= 1) acc += __shfl_down_sync(0xffffffffu, acc, o);
    if (lane == 0) atomicAdd(out, acc * (1.0f / NN));
}

// ---------------- launch ------------------------------------------------------
extern "C" void kernel_launch(void* const* d_in, const int* in_sizes, int n_in,
                              void* d_out, int out_size) {
    const float* x   = (const float*)d_in[0];
    const void*  ei  = d_in[1];                 // int32 or int64 — probed on device
    const float* W1  = (const float*)d_in[2];
    const float* b1  = (const float*)d_in[3];
    const float* W2  = (const float*)d_in[4];
    const float* b2  = (const float*)d_in[5];
    const float* Wfc = (const float*)d_in[6];
    const float* bfc = (const float*)d_in[7];
    float* out = (float*)d_out;
    (void)in_sizes; (void)n_in; (void)out_size;

    // dtype probe + CSR build
    k_detect<<<1, 256>>>(ei);
    k_init  <<<(NN + 255) / 256, 256>>>();
    k_count <<<(NE + 255) / 256, 256>>>(ei);
    k_isd   <<<(NN + 255) / 256, 256>>>();
    k_scan  <<<1, 1024>>>();
    k_fill  <<<(NE + 255) / 256, 256>>>(ei);

    // layer 1
    sgemm<true><<<dim3(256 / 64, (NN + 63) / 64), 256>>>(x, W1);
    k_agg<true><<<(NN + 7) / 8, 256>>>(b1);

    // layer 2
    sgemm<false><<<dim3(128 / 64, (NN + 63) / 64), 256>>>(nullptr, W2);
    k_agg<false><<<(NN + 7) / 8, 256>>>(b2);

    // pool + fc
    k_out_init<<<1, 1>>>(bfc, out);
    k_pool<<<1184, 256>>>(Wfc, out);
}

// round 5
// speedup vs baseline: 1.2695x; 1.2695x over previous
#include <cuda_runtime.h>
#include <cstdint>
#include <cstddef>

static constexpr int NN = 50000;   // nodes
static constexpr int NE = 800000;  // edges
// features: 128 -> 256 -> 128

// ---------------- scratch (device globals; no allocation allowed) -----------
__device__ int   g_is64;                     // edge_index dtype flag
__device__ int   g_cnt[NN];                  // in-degree (no self-loop)
__device__ int   g_cur[NN];                  // fill cursors
__device__ int   g_row[NN];                  // CSR row starts
__device__ int   g_csr[NE];                  // CSR src indices
__device__ float g_isd[NN];                  // 1/sqrt(deg), deg incl self-loop
__device__ float g_t1[(size_t)NN * 256];     // x @ W1
__device__ float g_z1[(size_t)NN * 256];     // relu(agg1 + b1)
__device__ float g_t2[(size_t)NN * 128];     // z1 @ W2
__device__ float g_z2[(size_t)NN * 128];     // relu(agg2 + b2)

// ---------------- edge_index dtype probe -------------------------------------
__global__ void k_detect(const void* __restrict__ ei) {
    __shared__ int bad;
    if (threadIdx.x == 0) bad = 0;
    __syncthreads();
    const long long* p = (const long long*)ei;
    for (int i = threadIdx.x; i < 1024; i += blockDim.x) {
        long long v = p[i];
        if (v < 0 || v >= NN) bad = 1;
    }
    __syncthreads();
    if (threadIdx.x == 0) g_is64 = bad ? 0 : 1;
}

__device__ __forceinline__ int edge_at(const void* __restrict__ ei, int idx) {
    if (g_is64) return (int)((const long long*)ei)[idx];
    return ((const int*)ei)[idx];
}

// ---------------- degree / CSR build ----------------------------------------
__global__ void k_init() {
    int i = blockIdx.x * blockDim.x + threadIdx.x;
    if (i < NN) { g_cnt[i] = 0; g_cur[i] = 0; }
}

__global__ void k_count(const void* __restrict__ ei) {
    int e = blockIdx.x * blockDim.x + threadIdx.x;
    if (e < NE) atomicAdd(&g_cnt[edge_at(ei, NE + e)], 1);
}

__global__ void k_isd() {
    int i = blockIdx.x * blockDim.x + threadIdx.x;
    if (i < NN) g_isd[i] = rsqrtf(1.0f + (float)g_cnt[i]);
}

// single-block exclusive scan of g_cnt -> g_row
__global__ void __launch_bounds__(1024) k_scan() {
    __shared__ int sh[2][1024];
    const int t  = threadIdx.x;
    const int CH = (NN + 1023) / 1024;   // 49
    const int b0 = t * CH;

    int local = 0;
    for (int i = 0; i < CH; i++) {
        int idx = b0 + i;
        if (idx < NN) local += g_cnt[idx];
    }
    int cur = 0;
    sh[cur][t] = local;
    __syncthreads();
    for (int off = 1; off < 1024; off <<= 1) {
        int nxt = cur ^ 1;
        int v = sh[cur][t];
        if (t >= off) v += sh[cur][t - off];
        sh[nxt][t] = v;
        __syncthreads();
        cur = nxt;
    }
    int run = (t == 0) ? 0 : sh[cur][t - 1];
    for (int i = 0; i < CH; i++) {
        int idx = b0 + i;
        if (idx < NN) { g_row[idx] = run; run += g_cnt[idx]; }
    }
}

__global__ void k_fill(const void* __restrict__ ei) {
    int e = blockIdx.x * blockDim.x + threadIdx.x;
    if (e >= NE) return;
    int s = edge_at(ei, e);
    int d = edge_at(ei, NE + e);
    int pos = g_row[d] + atomicAdd(&g_cur[d], 1);
    g_csr[pos] = s;
}

// ---------------- tf32 tensor-core GEMM --------------------------------------
// C[M,N] = A[M,K] @ W[K,N] via mma.sync.m16n8k8.tf32, fp32 accumulate.
// Block tile 128x64xBK32, 8 warps (4M x 2N), warp tile 32x32.
__device__ __forceinline__ uint32_t f2tf32(float f) {
    uint32_t o;
    asm("cvt.rna.tf32.f32 %0, %1;" : "=r"(o) : "f"(f));
    return o;
}

__device__ __forceinline__ void mma_tf32(float c[4], const uint32_t a[4],
                                         const uint32_t b[2]) {
    asm volatile(
        "mma.sync.aligned.m16n8k8.row.col.f32.tf32.tf32.f32 "
        "{%0,%1,%2,%3}, {%4,%5,%6,%7}, {%8,%9}, {%0,%1,%2,%3};"
        : "+f"(c[0]), "+f"(c[1]), "+f"(c[2]), "+f"(c[3])
        : "r"(a[0]), "r"(a[1]), "r"(a[2]), "r"(a[3]),
          "r"(b[0]), "r"(b[1]));
}

template <bool L1>
__global__ void __launch_bounds__(256)
tgemm(const float* __restrict__ Aext, const float* __restrict__ W) {
    constexpr int K   = L1 ? 128 : 256;
    constexpr int N   = L1 ? 256 : 128;
    constexpr int BM  = 128, BN = 64, BK = 32;
    constexpr int LDA = BK + 4;   // 36: frag loads hit 32 distinct banks
    constexpr int LDB = BN + 8;   // 72: frag loads hit 32 distinct banks
    constexpr int KT  = K / BK;

    const float* __restrict__ A = L1 ? Aext : g_z1;
    float* __restrict__       C = L1 ? g_t1 : g_t2;

    __shared__ uint32_t As[BM * LDA];
    __shared__ uint32_t Bs[BK * LDB];

    const int tid  = threadIdx.x;
    const int lane = tid & 31;
    const int wid  = tid >> 5;
    const int wm   = wid & 3;          // warp M index (0..3)
    const int wn   = wid >> 2;         // warp N index (0..1)
    const int gID  = lane >> 2;        // group id 0..7
    const int tg   = lane & 3;         // thread-in-group 0..3

    const int bm0 = blockIdx.y * BM;
    const int bn0 = blockIdx.x * BN;

    float c[2][4][4] = {};             // 2 m-frags x 4 n-frags x 4 regs

    for (int kt = 0; kt < KT; kt++) {
        // stage A: 128x32 floats = 1024 float4, 4 per thread
        #pragma unroll
        for (int i = 0; i < 4; i++) {
            int idx = tid + i * 256;
            int r   = idx >> 3;          // /8
            int c4  = (idx & 7) * 4;
            int rg  = bm0 + r;
            float4 v = make_float4(0.f, 0.f, 0.f, 0.f);
            if (rg < NN)
                v = *(const float4*)(A + (size_t)rg * K + kt * BK + c4);
            uint32_t* d = &As[r * LDA + c4];
            d[0] = f2tf32(v.x); d[1] = f2tf32(v.y);
            d[2] = f2tf32(v.z); d[3] = f2tf32(v.w);
        }
        // stage B: 32x64 floats = 512 float4, 2 per thread
        #pragma unroll
        for (int i = 0; i < 2; i++) {
            int idx = tid + i * 256;
            int r   = idx >> 4;          // /16
            int c4  = (idx & 15) * 4;
            float4 v = *(const float4*)(W + (size_t)(kt * BK + r) * N + bn0 + c4);
            uint32_t* d = &Bs[r * LDB + c4];
            d[0] = f2tf32(v.x); d[1] = f2tf32(v.y);
            d[2] = f2tf32(v.z); d[3] = f2tf32(v.w);
        }
        __syncthreads();

        #pragma unroll
        for (int kk = 0; kk < BK / 8; kk++) {
            uint32_t a[2][4], b[4][2];
            #pragma unroll
            for (int mi = 0; mi < 2; mi++) {
                int rb = wm * 32 + mi * 16 + gID;
                int kb = kk * 8 + tg;
                a[mi][0] = As[rb * LDA + kb];
                a[mi][1] = As[(rb + 8) * LDA + kb];
                a[mi][2] = As[rb * LDA + kb + 4];
                a[mi][3] = As[(rb + 8) * LDA + kb + 4];
            }
            #pragma unroll
            for (int ni = 0; ni < 4; ni++) {
                int col = wn * 32 + ni * 8 + gID;
                int kb  = kk * 8 + tg;
                b[ni][0] = Bs[kb * LDB + col];
                b[ni][1] = Bs[(kb + 4) * LDB + col];
            }
            #pragma unroll
            for (int mi = 0; mi < 2; mi++)
                #pragma unroll
                for (int ni = 0; ni < 4; ni++)
                    mma_tf32(c[mi][ni], a[mi], b[ni]);
        }
        __syncthreads();
    }

    // epilogue: c0/c1 -> (row, col), c2/c3 -> (row+8, col)
    #pragma unroll
    for (int mi = 0; mi < 2; mi++) {
        int r0 = bm0 + wm * 32 + mi * 16 + gID;
        #pragma unroll
        for (int ni = 0; ni < 4; ni++) {
            int col = bn0 + wn * 32 + ni * 8 + tg * 2;
            if (r0 < NN)
                *(float2*)(C + (size_t)r0 * N + col) =
                    make_float2(c[mi][ni][0], c[mi][ni][1]);
            if (r0 + 8 < NN)
                *(float2*)(C + (size_t)(r0 + 8) * N + col) =
                    make_float2(c[mi][ni][2], c[mi][ni][3]);
        }
    }
}

// ---------------- aggregation: warp-per-node CSR gather ----------------------
template <bool L1>
__global__ void __launch_bounds__(256)
k_agg(const float* __restrict__ bias) {
    constexpr int F  = L1 ? 256 : 128;
    constexpr int NV = F / 128;                    // float4 per lane
    const float* __restrict__ h = L1 ? g_t1 : g_t2;
    float* __restrict__       z = L1 ? g_z1 : g_z2;

    const int warp = threadIdx.x >> 5;
    const int lane = threadIdx.x & 31;
    const int node = blockIdx.x * 8 + warp;
    if (node >= NN) return;

    const float sd = g_isd[node];
    float4 acc[NV];
    {
        const float4* hd = (const float4*)(h + (size_t)node * F);
        const float w = sd * sd;
        #pragma unroll
        for (int v = 0; v < NV; v++) {
            float4 t = hd[lane + 32 * v];
            acc[v] = make_float4(t.x * w, t.y * w, t.z * w, t.w * w);
        }
    }

    const int beg = g_row[node];
    const int cnt = g_cnt[node];
    int e = 0;
    for (; e + 2 <= cnt; e += 2) {
        int s0 = g_csr[beg + e];
        int s1 = g_csr[beg + e + 1];
        float n0 = sd * g_isd[s0];
        float n1 = sd * g_isd[s1];
        const float4* h0 = (const float4*)(h + (size_t)s0 * F);
        const float4* h1 = (const float4*)(h + (size_t)s1 * F);
        #pragma unroll
        for (int v = 0; v < NV; v++) {
            float4 a = h0[lane + 32 * v];
            float4 b = h1[lane + 32 * v];
            acc[v].x += a.x * n0 + b.x * n1;
            acc[v].y += a.y * n0 + b.y * n1;
            acc[v].z += a.z * n0 + b.z * n1;
            acc[v].w += a.w * n0 + b.w * n1;
        }
    }
    if (e < cnt) {
        int s0 = g_csr[beg + e];
        float n0 = sd * g_isd[s0];
        const float4* h0 = (const float4*)(h + (size_t)s0 * F);
        #pragma unroll
        for (int v = 0; v < NV; v++) {
            float4 a = h0[lane + 32 * v];
            acc[v].x += a.x * n0;
            acc[v].y += a.y * n0;
            acc[v].z += a.z * n0;
            acc[v].w += a.w * n0;
        }
    }

    const float4* b4 = (const float4*)bias;
    float4* z4 = (float4*)(z + (size_t)node * F);
    #pragma unroll
    for (int v = 0; v < NV; v++) {
        float4 bb = b4[lane + 32 * v];
        float4 r;
        r.x = fmaxf(acc[v].x + bb.x, 0.f);
        r.y = fmaxf(acc[v].y + bb.y, 0.f);
        r.z = fmaxf(acc[v].z + bb.z, 0.f);
        r.w = fmaxf(acc[v].w + bb.w, 0.f);
        z4[lane + 32 * v] = r;
    }
}

// ---------------- final pool + fc --------------------------------------------
__global__ void k_out_init(const float* __restrict__ bfc, float* __restrict__ out) {
    out[0] = bfc[0];
}

__global__ void __launch_bounds__(256)
k_pool(const float* __restrict__ Wfc, float* __restrict__ out) {
    __shared__ float wf[128];
    int tid = threadIdx.x;
    if (tid < 128) wf[tid] = Wfc[tid];
    __syncthreads();

    int lane = tid & 31;
    int warp = tid >> 5;
    float acc = 0.f;

    for (int node = blockIdx.x * 8 + warp; node < NN; node += gridDim.x * 8) {
        const float4* row = (const float4*)(g_z2 + (size_t)node * 128);
        float4 v = row[lane];
        int f = lane * 4;
        acc += v.x * wf[f] + v.y * wf[f + 1] + v.z * wf[f + 2] + v.w * wf[f + 3];
    }
    #pragma unroll
    for (int o = 16; o; o >>= 1) acc += __shfl_down_sync(0xffffffffu, acc, o);
    if (lane == 0) atomicAdd(out, acc * (1.0f / NN));
}

// ---------------- launch ------------------------------------------------------
extern "C" void kernel_launch(void* const* d_in, const int* in_sizes, int n_in,
                              void* d_out, int out_size) {
    const float* x   = (const float*)d_in[0];
    const void*  ei  = d_in[1];                 // int32 or int64 — probed on device
    const float* W1  = (const float*)d_in[2];
    const float* b1  = (const float*)d_in[3];
    const float* W2  = (const float*)d_in[4];
    const float* b2  = (const float*)d_in[5];
    const float* Wfc = (const float*)d_in[6];
    const float* bfc = (const float*)d_in[7];
    float* out = (float*)d_out;
    (void)in_sizes; (void)n_in; (void)out_size;

    // dtype probe + CSR build
    k_detect<<<1, 256>>>(ei);
    k_init  <<<(NN + 255) / 256, 256>>>();
    k_count <<<(NE + 255) / 256, 256>>>(ei);
    k_isd   <<<(NN + 255) / 256, 256>>>();
    k_scan  <<<1, 1024>>>();
    k_fill  <<<(NE + 255) / 256, 256>>>(ei);

    // layer 1: t1 = x @ W1 (tf32 MMA), then CSR aggregate + bias + relu
    tgemm<true><<<dim3(256 / 64, (NN + 127) / 128), 256>>>(x, W1);
    k_agg<true><<<(NN + 7) / 8, 256>>>(b1);

    // layer 2
    tgemm<false><<<dim3(128 / 64, (NN + 127) / 128), 256>>>(nullptr, W2);
    k_agg<false><<<(NN + 7) / 8, 256>>>(b2);

    // pool + fc
    k_out_init<<<1, 1>>>(bfc, out);
    k_pool<<<1184, 256>>>(Wfc, out);
}

// round 6
// speedup vs baseline: 1.3271x; 1.0453x over previous
#include <cuda_runtime.h>
#include <cstdint>
#include <cstddef>

static constexpr int NN = 50000;   // nodes
static constexpr int NE = 800000;  // edges
// features: 128 -> 256 -> 128

// ---------------- scratch (device globals; no allocation allowed) -----------
__device__ int   g_is64;                     // edge_index dtype flag
__device__ int   g_cnt[NN];                  // in-degree (no self-loop)
__device__ int   g_cur[NN];                  // fill cursors
__device__ int   g_row[NN];                  // CSR row starts
__device__ int   g_csr[NE];                  // CSR src indices
__device__ float g_isd[NN];                  // 1/sqrt(deg), deg incl self-loop
__device__ float g_ax[(size_t)NN * 128];     // A_norm @ x
__device__ float g_z1[(size_t)NN * 256];     // relu(ax @ W1 + b1)
__device__ float g_t2[(size_t)NN * 128];     // z1 @ W2

// ---------------- edge_index dtype probe -------------------------------------
__global__ void k_detect(const void* __restrict__ ei) {
    __shared__ int bad;
    if (threadIdx.x == 0) bad = 0;
    __syncthreads();
    const long long* p = (const long long*)ei;
    for (int i = threadIdx.x; i < 1024; i += blockDim.x) {
        long long v = p[i];
        if (v < 0 || v >= NN) bad = 1;
    }
    __syncthreads();
    if (threadIdx.x == 0) g_is64 = bad ? 0 : 1;
}

__device__ __forceinline__ int edge_at(const void* __restrict__ ei, int idx) {
    if (g_is64) return (int)((const long long*)ei)[idx];
    return ((const int*)ei)[idx];
}

// ---------------- degree / CSR build ----------------------------------------
__global__ void k_init() {
    int i = blockIdx.x * blockDim.x + threadIdx.x;
    if (i < NN) { g_cnt[i] = 0; g_cur[i] = 0; }
}

__global__ void k_count(const void* __restrict__ ei) {
    int e = blockIdx.x * blockDim.x + threadIdx.x;
    if (e < NE) atomicAdd(&g_cnt[edge_at(ei, NE + e)], 1);
}

__global__ void k_isd() {
    int i = blockIdx.x * blockDim.x + threadIdx.x;
    if (i < NN) g_isd[i] = rsqrtf(1.0f + (float)g_cnt[i]);
}

// single-block exclusive scan of g_cnt -> g_row
__global__ void __launch_bounds__(1024) k_scan() {
    __shared__ int sh[2][1024];
    const int t  = threadIdx.x;
    const int CH = (NN + 1023) / 1024;   // 49
    const int b0 = t * CH;

    int local = 0;
    for (int i = 0; i < CH; i++) {
        int idx = b0 + i;
        if (idx < NN) local += g_cnt[idx];
    }
    int cur = 0;
    sh[cur][t] = local;
    __syncthreads();
    for (int off = 1; off < 1024; off <<= 1) {
        int nxt = cur ^ 1;
        int v = sh[cur][t];
        if (t >= off) v += sh[cur][t - off];
        sh[nxt][t] = v;
        __syncthreads();
        cur = nxt;
    }
    int run = (t == 0) ? 0 : sh[cur][t - 1];
    for (int i = 0; i < CH; i++) {
        int idx = b0 + i;
        if (idx < NN) { g_row[idx] = run; run += g_cnt[idx]; }
    }
}

__global__ void k_fill(const void* __restrict__ ei) {
    int e = blockIdx.x * blockDim.x + threadIdx.x;
    if (e >= NE) return;
    int s = edge_at(ei, e);
    int d = edge_at(ei, NE + e);
    int pos = g_row[d] + atomicAdd(&g_cur[d], 1);
    g_csr[pos] = s;
}

// ---------------- aggregation 1: ax = A_norm @ x (128 feat) ------------------
__global__ void __launch_bounds__(256)
k_aggX(const float* __restrict__ x) {
    const int warp = threadIdx.x >> 5;
    const int lane = threadIdx.x & 31;
    const int node = blockIdx.x * 8 + warp;
    if (node >= NN) return;

    const float sd = g_isd[node];
    float4 acc;
    {
        float4 t = ((const float4*)(x + (size_t)node * 128))[lane];
        const float w = sd * sd;
        acc = make_float4(t.x * w, t.y * w, t.z * w, t.w * w);
    }

    const int beg = g_row[node];
    const int cnt = g_cnt[node];
    int e = 0;
    for (; e + 2 <= cnt; e += 2) {
        int s0 = g_csr[beg + e];
        int s1 = g_csr[beg + e + 1];
        float n0 = sd * g_isd[s0];
        float n1 = sd * g_isd[s1];
        float4 a = ((const float4*)(x + (size_t)s0 * 128))[lane];
        float4 b = ((const float4*)(x + (size_t)s1 * 128))[lane];
        acc.x += a.x * n0 + b.x * n1;
        acc.y += a.y * n0 + b.y * n1;
        acc.z += a.z * n0 + b.z * n1;
        acc.w += a.w * n0 + b.w * n1;
    }
    if (e < cnt) {
        int s0 = g_csr[beg + e];
        float n0 = sd * g_isd[s0];
        float4 a = ((const float4*)(x + (size_t)s0 * 128))[lane];
        acc.x += a.x * n0; acc.y += a.y * n0;
        acc.z += a.z * n0; acc.w += a.w * n0;
    }

    ((float4*)(g_ax + (size_t)node * 128))[lane] = acc;
}

// ---------------- tf32 tensor-core GEMM --------------------------------------
// L1: C = relu(g_ax @ W1 + bias), K=128, N=256.  !L1: C = g_z1 @ W2, K=256, N=128.
__device__ __forceinline__ uint32_t f2tf32(float f) {
    uint32_t o;
    asm("cvt.rna.tf32.f32 %0, %1;" : "=r"(o) : "f"(f));
    return o;
}

__device__ __forceinline__ void mma_tf32(float c[4], const uint32_t a[4],
                                         const uint32_t b[2]) {
    asm volatile(
        "mma.sync.aligned.m16n8k8.row.col.f32.tf32.tf32.f32 "
        "{%0,%1,%2,%3}, {%4,%5,%6,%7}, {%8,%9}, {%0,%1,%2,%3};"
        : "+f"(c[0]), "+f"(c[1]), "+f"(c[2]), "+f"(c[3])
        : "r"(a[0]), "r"(a[1]), "r"(a[2]), "r"(a[3]),
          "r"(b[0]), "r"(b[1]));
}

template <bool L1>
__global__ void __launch_bounds__(256)
tgemm(const float* __restrict__ W, const float* __restrict__ bias) {
    constexpr int K   = L1 ? 128 : 256;
    constexpr int N   = L1 ? 256 : 128;
    constexpr int BM  = 128, BN = 64, BK = 32;
    constexpr int LDA = BK + 4;
    constexpr int LDB = BN + 8;
    constexpr int KT  = K / BK;

    const float* __restrict__ A = L1 ? g_ax : g_z1;
    float* __restrict__       C = L1 ? g_z1 : g_t2;

    __shared__ uint32_t As[BM * LDA];
    __shared__ uint32_t Bs[BK * LDB];

    const int tid  = threadIdx.x;
    const int lane = tid & 31;
    const int wid  = tid >> 5;
    const int wm   = wid & 3;
    const int wn   = wid >> 2;
    const int gID  = lane >> 2;
    const int tg   = lane & 3;

    const int bm0 = blockIdx.y * BM;
    const int bn0 = blockIdx.x * BN;

    float c[2][4][4] = {};

    for (int kt = 0; kt < KT; kt++) {
        #pragma unroll
        for (int i = 0; i < 4; i++) {
            int idx = tid + i * 256;
            int r   = idx >> 3;
            int c4  = (idx & 7) * 4;
            int rg  = bm0 + r;
            float4 v = make_float4(0.f, 0.f, 0.f, 0.f);
            if (rg < NN)
                v = *(const float4*)(A + (size_t)rg * K + kt * BK + c4);
            uint32_t* d = &As[r * LDA + c4];
            d[0] = f2tf32(v.x); d[1] = f2tf32(v.y);
            d[2] = f2tf32(v.z); d[3] = f2tf32(v.w);
        }
        #pragma unroll
        for (int i = 0; i < 2; i++) {
            int idx = tid + i * 256;
            int r   = idx >> 4;
            int c4  = (idx & 15) * 4;
            float4 v = *(const float4*)(W + (size_t)(kt * BK + r) * N + bn0 + c4);
            uint32_t* d = &Bs[r * LDB + c4];
            d[0] = f2tf32(v.x); d[1] = f2tf32(v.y);
            d[2] = f2tf32(v.z); d[3] = f2tf32(v.w);
        }
        __syncthreads();

        #pragma unroll
        for (int kk = 0; kk < BK / 8; kk++) {
            uint32_t a[2][4], b[4][2];
            #pragma unroll
            for (int mi = 0; mi < 2; mi++) {
                int rb = wm * 32 + mi * 16 + gID;
                int kb = kk * 8 + tg;
                a[mi][0] = As[rb * LDA + kb];
                a[mi][1] = As[(rb + 8) * LDA + kb];
                a[mi][2] = As[rb * LDA + kb + 4];
                a[mi][3] = As[(rb + 8) * LDA + kb + 4];
            }
            #pragma unroll
            for (int ni = 0; ni < 4; ni++) {
                int col = wn * 32 + ni * 8 + gID;
                int kb  = kk * 8 + tg;
                b[ni][0] = Bs[kb * LDB + col];
                b[ni][1] = Bs[(kb + 4) * LDB + col];
            }
            #pragma unroll
            for (int mi = 0; mi < 2; mi++)
                #pragma unroll
                for (int ni = 0; ni < 4; ni++)
                    mma_tf32(c[mi][ni], a[mi], b[ni]);
        }
        __syncthreads();
    }

    #pragma unroll
    for (int mi = 0; mi < 2; mi++) {
        int r0 = bm0 + wm * 32 + mi * 16 + gID;
        #pragma unroll
        for (int ni = 0; ni < 4; ni++) {
            int col = bn0 + wn * 32 + ni * 8 + tg * 2;
            float2 v0 = make_float2(c[mi][ni][0], c[mi][ni][1]);
            float2 v1 = make_float2(c[mi][ni][2], c[mi][ni][3]);
            if (L1) {
                float bx = bias[col], by = bias[col + 1];
                v0.x = fmaxf(v0.x + bx, 0.f); v0.y = fmaxf(v0.y + by, 0.f);
                v1.x = fmaxf(v1.x + bx, 0.f); v1.y = fmaxf(v1.y + by, 0.f);
            }
            if (r0 < NN)     *(float2*)(C + (size_t)r0 * N + col) = v0;
            if (r0 + 8 < NN) *(float2*)(C + (size_t)(r0 + 8) * N + col) = v1;
        }
    }
}

// ---------------- aggregation 2 + bias + relu + pool + fc --------------------
// per node: r = relu(agg(t2) + b2); out += dot(r, Wfc)/NN
__global__ void __launch_bounds__(256)
k_agg2(const float* __restrict__ bias, const float* __restrict__ Wfc,
       float* __restrict__ out) {
    const int warp = threadIdx.x >> 5;
    const int lane = threadIdx.x & 31;
    const int node = blockIdx.x * 8 + warp;
    if (node >= NN) return;

    const float* __restrict__ h = g_t2;
    const float sd = g_isd[node];
    float4 acc;
    {
        float4 t = ((const float4*)(h + (size_t)node * 128))[lane];
        const float w = sd * sd;
        acc = make_float4(t.x * w, t.y * w, t.z * w, t.w * w);
    }

    const int beg = g_row[node];
    const int cnt = g_cnt[node];
    int e = 0;
    for (; e + 2 <= cnt; e += 2) {
        int s0 = g_csr[beg + e];
        int s1 = g_csr[beg + e + 1];
        float n0 = sd * g_isd[s0];
        float n1 = sd * g_isd[s1];
        float4 a = ((const float4*)(h + (size_t)s0 * 128))[lane];
        float4 b = ((const float4*)(h + (size_t)s1 * 128))[lane];
        acc.x += a.x * n0 + b.x * n1;
        acc.y += a.y * n0 + b.y * n1;
        acc.z += a.z * n0 + b.z * n1;
        acc.w += a.w * n0 + b.w * n1;
    }
    if (e < cnt) {
        int s0 = g_csr[beg + e];
        float n0 = sd * g_isd[s0];
        float4 a = ((const float4*)(h + (size_t)s0 * 128))[lane];
        acc.x += a.x * n0; acc.y += a.y * n0;
        acc.z += a.z * n0; acc.w += a.w * n0;
    }

    float4 bb = ((const float4*)bias)[lane];
    float4 wf = ((const float4*)Wfc)[lane];
    float dot =
        fmaxf(acc.x + bb.x, 0.f) * wf.x +
        fmaxf(acc.y + bb.y, 0.f) * wf.y +
        fmaxf(acc.z + bb.z, 0.f) * wf.z +
        fmaxf(acc.w + bb.w, 0.f) * wf.w;

    #pragma unroll
    for (int o = 16; o; o >>= 1) dot += __shfl_down_sync(0xffffffffu, dot, o);
    if (lane == 0) atomicAdd(out, dot * (1.0f / NN));
}

__global__ void k_out_init(const float* __restrict__ bfc, float* __restrict__ out) {
    out[0] = bfc[0];
}

// ---------------- launch ------------------------------------------------------
extern "C" void kernel_launch(void* const* d_in, const int* in_sizes, int n_in,
                              void* d_out, int out_size) {
    const float* x   = (const float*)d_in[0];
    const void*  ei  = d_in[1];                 // int32 or int64 — probed on device
    const float* W1  = (const float*)d_in[2];
    const float* b1  = (const float*)d_in[3];
    const float* W2  = (const float*)d_in[4];
    const float* b2  = (const float*)d_in[5];
    const float* Wfc = (const float*)d_in[6];
    const float* bfc = (const float*)d_in[7];
    float* out = (float*)d_out;
    (void)in_sizes; (void)n_in; (void)out_size;

    // dtype probe + CSR build
    k_detect<<<1, 256>>>(ei);
    k_init  <<<(NN + 255) / 256, 256>>>();
    k_count <<<(NE + 255) / 256, 256>>>(ei);
    k_isd   <<<(NN + 255) / 256, 256>>>();
    k_scan  <<<1, 1024>>>();
    k_fill  <<<(NE + 255) / 256, 256>>>(ei);

    // layer 1: aggregate x first (narrower), then fused GEMM+bias+relu
    k_aggX<<<(NN + 7) / 8, 256>>>(x);
    tgemm<true><<<dim3(256 / 64, (NN + 127) / 128), 256>>>(W1, b1);

    // layer 2: transform first (output is narrower), then fused agg+pool+fc
    tgemm<false><<<dim3(128 / 64, (NN + 127) / 128), 256>>>(W2, nullptr);
    k_out_init<<<1, 1>>>(bfc, out);
    k_agg2<<<(NN + 7) / 8, 256>>>(b2, Wfc, out);
}